// round 2
// baseline (speedup 1.0000x reference)
#include <cuda_runtime.h>
#include <math.h>

// dims: N=64, C=64, T=512, V=25, S=3, I=16
// ---------------- device scratch (no cudaMalloc allowed) ----------------
__device__ float g_fa[192u * 8192u * 32u];    // [n*3+s][t*16+i][v32]  201MB
__device__ float g_fb[192u * 8192u * 32u];
__device__ float g_Apart[1536u * 1024u];      // [ns*8+seg][v32*32]
__device__ float g_Aeff[192 * 625];           // [n*3+s][v][w]
__device__ float g_Wdt[3 * 64 * 64];          // [s][c][o]
__device__ float g_Wt9[9 * 64 * 64];          // [k][c][o]
__device__ float g_y[52428800u];              // pre-BN y; later reused for TCN z
__device__ float g_y2[52428800u];             // post BN1+residual+relu
__device__ float g_bnpart[64 * 32 * 2];
__device__ float g_stats[256];                // [off+c]=mean, [off+64+c]=rstd
__device__ float g_meanT[64 * 64 * 25];
__device__ float g_gs[64 * 25];               // 1+sigmoid spatial gate
__device__ float g_meanV[64 * 64 * 512];
__device__ float g_gt[64 * 512];              // 1+sigmoid temporal gate
__device__ float g_gc[64 * 64];               // 1+sigmoid channel gate

// ---------------- weight prep (transposes) ----------------
__global__ void k_prep(const float* __restrict__ Wd, const float* __restrict__ tw) {
    int tid = blockIdx.x * 256 + threadIdx.x;
    int stride = gridDim.x * 256;
    // Wdt[s][c][o] = Wd[s][o][c]
    for (int i = tid; i < 3 * 64 * 64; i += stride) {
        int s = i / 4096, r = i % 4096, c = r / 64, o = r % 64;
        g_Wdt[i] = Wd[s * 4096 + o * 64 + c];
    }
    // Wt9[k][c][o] = tcn_w[o][c][k][0]
    for (int i = tid; i < 9 * 64 * 64; i += stride) {
        int k = i / 4096, r = i % 4096, c = r / 64, o = r % 64;
        g_Wt9[i] = tw[o * 576 + c * 9 + k];
    }
}

// ---------------- fa/fb projections: [I=16,C=64] x [C, T*V] per (n,s) ----------------
// block: (tc of 8 t's, s, n); 256 threads = 32 abi x 8 tg; each thread: 32 v accums
__global__ void __launch_bounds__(256) k_fab(
    const float* __restrict__ x, const float* __restrict__ Wa, const float* __restrict__ ba,
    const float* __restrict__ Wb, const float* __restrict__ bb)
{
    extern __shared__ float sm[];
    float* xs  = sm;          // [c=64][t=8][v32]  16384 floats
    float* Wab = sm + 16384;  // [abi=32][stride 65]
    int tcb = blockIdx.x, s = blockIdx.y, n = blockIdx.z;
    int t0 = tcb * 8, tid = threadIdx.x;

    for (int idx = tid; idx < 16384; idx += 256) {
        int c = idx >> 8, r = idx & 255, t = r >> 5, v = r & 31;
        float val = 0.f;
        if (v < 25) val = x[(((size_t)n * 64 + c) * 512 + (t0 + t)) * 25 + v];
        xs[idx] = val;
    }
    for (int idx = tid; idx < 2048; idx += 256) {
        int r = idx >> 6, c = idx & 63;
        Wab[r * 65 + c] = (r < 16) ? Wa[s * 1024 + r * 64 + c]
                                   : Wb[s * 1024 + (r - 16) * 64 + c];
    }
    __syncthreads();

    int abi = tid & 31, tg = tid >> 5;
    float bias = (abi < 16) ? ba[s * 16 + abi] : bb[s * 16 + (abi - 16)];
    float acc[32];
#pragma unroll
    for (int m = 0; m < 32; m++) acc[m] = bias;

    for (int c = 0; c < 64; c++) {
        float w = Wab[abi * 65 + c];
        const float4* xr = (const float4*)&xs[c * 256 + tg * 32];
#pragma unroll
        for (int m = 0; m < 8; m++) {
            float4 X = xr[m];
            acc[4 * m + 0] += w * X.x; acc[4 * m + 1] += w * X.y;
            acc[4 * m + 2] += w * X.z; acc[4 * m + 3] += w * X.w;
        }
    }
    float* outp = (abi < 16) ? g_fa : g_fb;
    size_t base = (((size_t)(n * 3 + s)) * 8192 + (size_t)(t0 + tg) * 16 + (abi & 15)) * 32;
    float4* o4 = (float4*)&outp[base];
#pragma unroll
    for (int m = 0; m < 8; m++)
        o4[m] = make_float4(acc[4 * m], acc[4 * m + 1], acc[4 * m + 2], acc[4 * m + 3]);
}

// ---------------- Gram partials: A[v,w] = sum_k fa[k,v]*fb[k,w] ----------------
__global__ void __launch_bounds__(256) k_gram() {
    __shared__ float fas[2048], fbs[2048];
    int ns = blockIdx.x, seg = blockIdx.y, tid = threadIdx.x;
    int v = tid >> 3, w4 = (tid & 7) * 4;
    float a0 = 0, a1 = 0, a2 = 0, a3 = 0;
    size_t base = (size_t)ns * 8192u * 32u + (size_t)seg * 1024u * 32u;
    for (int kc = 0; kc < 1024; kc += 64) {
        for (int idx = tid; idx < 2048; idx += 256) {
            fas[idx] = g_fa[base + (size_t)kc * 32 + idx];
            fbs[idx] = g_fb[base + (size_t)kc * 32 + idx];
        }
        __syncthreads();
#pragma unroll 4
        for (int kk = 0; kk < 64; kk++) {
            float fav = fas[kk * 32 + v];
            float4 f4 = *(const float4*)&fbs[kk * 32 + w4];
            a0 += fav * f4.x; a1 += fav * f4.y; a2 += fav * f4.z; a3 += fav * f4.w;
        }
        __syncthreads();
    }
    float* p = &g_Apart[((size_t)ns * 8 + seg) * 1024 + v * 32 + w4];
    p[0] = a0; p[1] = a1; p[2] = a2; p[3] = a3;
}

__global__ void k_gram2(const float* __restrict__ PA, const float* __restrict__ alpha) {
    int ns = blockIdx.x; int s = ns % 3;
    float al = alpha[0];
    for (int p = threadIdx.x; p < 625; p += 256) {
        int v = p / 25, w = p % 25;
        float sum = 0;
        for (int seg = 0; seg < 8; seg++)
            sum += g_Apart[((size_t)ns * 8 + seg) * 1024 + v * 32 + w];
        float A1 = tanhf(sum * (1.0f / 8192.0f));
        g_Aeff[ns * 625 + p] = PA[s * 625 + p] + al * A1;
    }
}

// ---------------- GCN: y[o,t,w] = sum_s Wd_s[o,c] * (x[c,t,v] Ae_s[v,w]) ----------------
// block (tc of 4 t, n); 256 thr; tw = t*28+w (padded)
#define ZST 112
__global__ void __launch_bounds__(256) k_gcn(const float* __restrict__ x) {
    extern __shared__ float sm[];
    float* xT = sm;                  // [t*25+v][stride 68 c]  6800
    float* zs = sm + 6800;           // [c][tw stride 112]     7168
    float* wd = sm + 6800 + 7168;    // [c][o]                 4096
    float* ae = sm + 6800 + 7168 + 4096; // [v][w stride 28]   700
    int tcb = blockIdx.x, n = blockIdx.y;
    int t0 = tcb * 4, tid = threadIdx.x;

    for (int idx = tid; idx < 6400; idx += 256) {
        int c = idx / 100, r = idx % 100, t = r / 25, v = r % 25;
        xT[(t * 25 + v) * 68 + c] = x[(((size_t)n * 64 + c) * 512 + t0 + t) * 25 + v];
    }
    // zs-phase map
    int cg = tid >> 4, tg2 = tid & 15;
    int zt[7], zw[7];
#pragma unroll
    for (int j = 0; j < 7; j++) { int tw = tg2 + 16 * j; zt[j] = tw / 28; zw[j] = tw % 28; }
    // gemm-phase map
    int ot = tid & 15, twt = tid >> 4;
    int gt_[7], gw[7];
#pragma unroll
    for (int j = 0; j < 7; j++) { int tw = twt + 16 * j; gt_[j] = tw / 28; gw[j] = tw % 28; }

    float acc[4][7];
#pragma unroll
    for (int i = 0; i < 4; i++)
#pragma unroll
        for (int j = 0; j < 7; j++) acc[i][j] = 0.f;

    for (int s = 0; s < 3; s++) {
        for (int idx = tid; idx < 700; idx += 256) {
            int v = idx / 28, w = idx % 28;
            ae[idx] = (w < 25) ? g_Aeff[(size_t)(n * 3 + s) * 625 + v * 25 + w] : 0.f;
        }
        for (int idx = tid; idx < 4096; idx += 256) wd[idx] = g_Wdt[s * 4096 + idx];
        __syncthreads();
        // zs[c][tw] = sum_v x[c,t,v]*Ae[v,w]
        {
            float tmp[4][7];
#pragma unroll
            for (int i = 0; i < 4; i++)
#pragma unroll
                for (int j = 0; j < 7; j++) tmp[i][j] = 0.f;
            for (int v = 0; v < 25; v++) {
#pragma unroll
                for (int j = 0; j < 7; j++) {
                    float4 X = *(const float4*)&xT[(zt[j] * 25 + v) * 68 + 4 * cg];
                    float a = ae[v * 28 + zw[j]];
                    tmp[0][j] += X.x * a; tmp[1][j] += X.y * a;
                    tmp[2][j] += X.z * a; tmp[3][j] += X.w * a;
                }
            }
#pragma unroll
            for (int i = 0; i < 4; i++)
#pragma unroll
                for (int j = 0; j < 7; j++)
                    zs[(4 * cg + i) * ZST + tg2 + 16 * j] = tmp[i][j];
        }
        __syncthreads();
        // y[o][tw] += Wd[o][c]*zs[c][tw]
        for (int c = 0; c < 64; c++) {
            float4 w4 = *(const float4*)&wd[c * 64 + 4 * ot];
#pragma unroll
            for (int j = 0; j < 7; j++) {
                float z = zs[c * ZST + twt + 16 * j];
                acc[0][j] += w4.x * z; acc[1][j] += w4.y * z;
                acc[2][j] += w4.z * z; acc[3][j] += w4.w * z;
            }
        }
        __syncthreads();
    }
#pragma unroll
    for (int j = 0; j < 7; j++) {
        if (gw[j] < 25) {
#pragma unroll
            for (int i = 0; i < 4; i++)
                g_y[(((size_t)n * 64 + 4 * ot + i) * 512 + t0 + gt_[j]) * 25 + gw[j]] = acc[i][j];
        }
    }
}

// ---------------- BN stats on g_y (shared by BN1 and BN2) ----------------
__global__ void k_bnstat() {
    __shared__ float s1[256], s2[256];
    int c = blockIdx.x, p = blockIdx.y, tid = threadIdx.x;
    float a = 0, b = 0;
    for (int idx = tid; idx < 2 * 12800; idx += 256) {
        int nn = p * 2 + idx / 12800, r = idx % 12800;
        float v = g_y[(size_t)(nn * 64 + c) * 12800 + r];
        a += v; b += v * v;
    }
    s1[tid] = a; s2[tid] = b; __syncthreads();
    for (int st = 128; st > 0; st >>= 1) {
        if (tid < st) { s1[tid] += s1[tid + st]; s2[tid] += s2[tid + st]; }
        __syncthreads();
    }
    if (tid == 0) {
        g_bnpart[(c * 32 + p) * 2] = s1[0];
        g_bnpart[(c * 32 + p) * 2 + 1] = s2[0];
    }
}

__global__ void k_bnfin(int off) {
    int c = threadIdx.x;
    if (c < 64) {
        float a = 0, b = 0;
        for (int p = 0; p < 32; p++) {
            a += g_bnpart[(c * 32 + p) * 2];
            b += g_bnpart[(c * 32 + p) * 2 + 1];
        }
        float m = a / 819200.0f;
        float var = b / 819200.0f - m * m;
        g_stats[off + c] = m;
        g_stats[off + 64 + c] = rsqrtf(var + 1e-5f);
    }
}

// out = relu(bn(g_y)+x) -> (sel? outext : g_y2)
__global__ void __launch_bounds__(256) k_bnapply(
    const float* __restrict__ gm, const float* __restrict__ bt,
    const float* __restrict__ x, float* __restrict__ outext, int sel, int off)
{
    size_t i4 = (size_t)blockIdx.x * 256 + threadIdx.x;
    size_t flat = i4 * 4;
    int c = (int)((flat / 12800) % 64);
    float m = g_stats[off + c], r = g_stats[off + 64 + c];
    float sc = r * gm[c];
    float sb = bt[c] - m * sc;
    float4 Y = *(const float4*)&g_y[flat];
    float4 X = *(const float4*)&x[flat];
    float4 O;
    O.x = fmaxf(Y.x * sc + sb + X.x, 0.f);
    O.y = fmaxf(Y.y * sc + sb + X.y, 0.f);
    O.z = fmaxf(Y.z * sc + sb + X.z, 0.f);
    O.w = fmaxf(Y.w * sc + sb + X.w, 0.f);
    float* dst = sel ? outext : g_y2;
    *(float4*)&dst[flat] = O;
}

// ---------------- attention chain ----------------
__global__ void k_meanT() {
    __shared__ float red[8 * 33];
    int nc = blockIdx.x, tid = threadIdx.x;
    int v = tid & 31, tg = tid >> 5;
    float a = 0;
    if (v < 25)
        for (int t = tg; t < 512; t += 8) a += g_y2[(size_t)nc * 12800 + t * 25 + v];
    red[tg * 33 + v] = a; __syncthreads();
    if (tid < 25) {
        float s = 0;
        for (int g = 0; g < 8; g++) s += red[g * 33 + tid];
        g_meanT[nc * 25 + tid] = s * (1.f / 512.f);
    }
}

__global__ void k_sattn(const float* __restrict__ saw, const float* __restrict__ sab) {
    int n = blockIdx.x, v = threadIdx.x;
    if (v < 25) {
        float acc = sab[0];
        for (int c = 0; c < 64; c++) {
            const float* m = &g_meanT[(n * 64 + c) * 25];
            const float* w = &saw[c * 25];
#pragma unroll
            for (int j = 0; j < 25; j++) {
                int vv = v + j - 12;
                if (vv >= 0 && vv < 25) acc += w[j] * m[vv];
            }
        }
        g_gs[n * 25 + v] = 1.f + 1.f / (1.f + expf(-acc));
    }
}

__global__ void __launch_bounds__(256) k_meanV() {
    __shared__ float sgs[25];
    int nc = blockIdx.x, tid = threadIdx.x;
    int n = nc >> 6;
    if (tid < 25) sgs[tid] = g_gs[n * 25 + tid];
    __syncthreads();
    for (int t = tid; t < 512; t += 256) {
        const float* row = &g_y2[(size_t)nc * 12800 + t * 25];
        float a = 0;
#pragma unroll
        for (int v = 0; v < 25; v++) a += row[v] * sgs[v];
        g_meanV[nc * 512 + t] = a * (1.f / 25.f);
    }
}

__global__ void k_tattn(const float* __restrict__ taw, const float* __restrict__ tab) {
    int n = blockIdx.x, tid = threadIdx.x;
    for (int t = tid; t < 512; t += 256) {
        float acc = tab[0];
        for (int c = 0; c < 64; c++) {
            const float* m = &g_meanV[(n * 64 + c) * 512];
            const float* w = &taw[c * 9];
#pragma unroll
            for (int j = 0; j < 9; j++) {
                int tt = t + j - 4;
                if (tt >= 0 && tt < 512) acc += w[j] * m[tt];
            }
        }
        g_gt[n * 512 + t] = 1.f + 1.f / (1.f + expf(-acc));
    }
}

__global__ void k_cse(const float* __restrict__ f1w, const float* __restrict__ f1b,
                      const float* __restrict__ f2w, const float* __restrict__ f2b) {
    __shared__ float sm3[64], sh[32];
    int n = blockIdx.x, c = threadIdx.x;
    const float* m = &g_meanV[(n * 64 + c) * 512];
    const float* gt = &g_gt[n * 512];
    float a = 0;
    for (int t = 0; t < 512; t++) a += m[t] * gt[t];
    sm3[c] = a * (1.f / 512.f);
    __syncthreads();
    if (c < 32) {
        float h = f1b[c];
        for (int k = 0; k < 64; k++) h += f1w[c * 64 + k] * sm3[k];
        sh[c] = fmaxf(h, 0.f);
    }
    __syncthreads();
    float o = f2b[c];
    for (int j = 0; j < 32; j++) o += f2w[c * 32 + j] * sh[j];
    g_gc[n * 64 + c] = 1.f + 1.f / (1.f + expf(-o));
}

// ---------------- TCN: z[o,t,v] = sum_{c,k} W[o,c,k] * (y2*gs*gt*gc)[c,t+k-4,v] ----------------
__global__ void __launch_bounds__(256) k_tcn() {
    extern __shared__ float sm[];
    float* yin = sm;          // [c=64][tl=12 stride 28] = 21504
    float* wk = sm + 21504;   // [c][o] 4096 ; first reused as gate stage
    int tcb = blockIdx.x, n = blockIdx.y;
    int t0 = tcb * 4, tid = threadIdx.x;

    // stage gates into wk area: [0..24]=gs, [32..43]=gt(tl), [64..127]=gc
    if (tid < 25) wk[tid] = g_gs[n * 25 + tid];
    if (tid >= 32 && tid < 44) {
        int tl = tid - 32, tin = t0 - 4 + tl;
        wk[tid] = (tin >= 0 && tin < 512) ? g_gt[n * 512 + tin] : 0.f;
    }
    if (tid >= 64 && tid < 128) wk[tid] = g_gc[n * 64 + (tid - 64)];
    __syncthreads();

    for (int idx = tid; idx < 21504; idx += 256) {
        int c = idx / 336, r = idx % 336, tl = r / 28, w = r % 28;
        int tin = t0 - 4 + tl;
        float val = 0.f;
        if (w < 25 && tin >= 0 && tin < 512) {
            val = g_y2[(((size_t)n * 64 + c) * 512 + tin) * 25 + w]
                * wk[w] * wk[32 + tl] * wk[64 + c];
        }
        yin[idx] = val;
    }

    int ot = tid & 15, twt = tid >> 4;
    int off[7], tj[7], wj[7];
#pragma unroll
    for (int j = 0; j < 7; j++) { int tw = twt + 16 * j; off[j] = tw; tj[j] = tw / 28; wj[j] = tw % 28; }
    float acc[4][7];
#pragma unroll
    for (int i = 0; i < 4; i++)
#pragma unroll
        for (int j = 0; j < 7; j++) acc[i][j] = 0.f;

    for (int k = 0; k < 9; k++) {
        __syncthreads();
        for (int idx = tid; idx < 4096; idx += 256) wk[idx] = g_Wt9[k * 4096 + idx];
        __syncthreads();
        for (int c = 0; c < 64; c++) {
            float4 w4 = *(const float4*)&wk[c * 64 + 4 * ot];
            const float* yrow = &yin[c * 336 + 28 * k];
#pragma unroll
            for (int j = 0; j < 7; j++) {
                float z = yrow[off[j]];
                acc[0][j] += w4.x * z; acc[1][j] += w4.y * z;
                acc[2][j] += w4.z * z; acc[3][j] += w4.w * z;
            }
        }
    }
#pragma unroll
    for (int j = 0; j < 7; j++) {
        if (wj[j] < 25) {
#pragma unroll
            for (int i = 0; i < 4; i++)
                g_y[(((size_t)n * 64 + 4 * ot + i) * 512 + t0 + tj[j]) * 25 + wj[j]] = acc[i][j];
        }
    }
}

// ---------------- launcher ----------------
extern "C" void kernel_launch(void* const* d_in, const int* in_sizes, int n_in,
                              void* d_out, int out_size) {
    const float* x   = (const float*)d_in[0];
    const float* PA  = (const float*)d_in[1];
    const float* alp = (const float*)d_in[2];
    const float* Wa  = (const float*)d_in[3];
    const float* ba  = (const float*)d_in[4];
    const float* Wb  = (const float*)d_in[5];
    const float* bb  = (const float*)d_in[6];
    const float* Wd  = (const float*)d_in[7];
    const float* bng = (const float*)d_in[9];
    const float* bnb = (const float*)d_in[10];
    const float* saw = (const float*)d_in[11];
    const float* sab = (const float*)d_in[12];
    const float* taw = (const float*)d_in[13];
    const float* tab = (const float*)d_in[14];
    const float* f1w = (const float*)d_in[15];
    const float* f1b = (const float*)d_in[16];
    const float* f2w = (const float*)d_in[17];
    const float* f2b = (const float*)d_in[18];
    const float* tw  = (const float*)d_in[19];
    const float* tbg = (const float*)d_in[21];
    const float* tbb = (const float*)d_in[22];
    float* out = (float*)d_out;

    cudaFuncSetAttribute(k_fab, cudaFuncAttributeMaxDynamicSharedMemorySize, 73856);
    cudaFuncSetAttribute(k_gcn, cudaFuncAttributeMaxDynamicSharedMemorySize, 75056);
    cudaFuncSetAttribute(k_tcn, cudaFuncAttributeMaxDynamicSharedMemorySize, 102400);

    k_prep<<<32, 256>>>(Wd, tw);
    k_fab<<<dim3(64, 3, 64), 256, 73856>>>(x, Wa, ba, Wb, bb);
    k_gram<<<dim3(192, 8), 256>>>();
    k_gram2<<<192, 256>>>(PA, alp);
    k_gcn<<<dim3(128, 64), 256, 75056>>>(x);
    k_bnstat<<<dim3(64, 32), 256>>>();
    k_bnfin<<<1, 64>>>(0);
    k_bnapply<<<51200, 256>>>(bng, bnb, x, out, 0, 0);
    k_meanT<<<4096, 256>>>();
    k_sattn<<<64, 32>>>(saw, sab);
    k_meanV<<<4096, 256>>>();
    k_tattn<<<64, 256>>>(taw, tab);
    k_cse<<<64, 64>>>(f1w, f1b, f2w, f2b);
    k_tcn<<<dim3(128, 64), 256, 102400>>>();
    k_bnstat<<<dim3(64, 32), 256>>>();
    k_bnfin<<<1, 64>>>(128);
    k_bnapply<<<51200, 256>>>(tbg, tbb, x, out, 1, 128);
}

// round 4
// speedup vs baseline: 1.0003x; 1.0003x over previous
#include <cuda_runtime.h>
#include <math.h>

// dims: N=64, C=64, T=512, V=25, S=3, I=16
// ---------------- device scratch (no cudaMalloc allowed) ----------------
__device__ float g_Apart[1536u * 1024u];      // [(n*3+s)*8+seg][v32*32]
__device__ float g_Aeff[192 * 625];           // [n*3+s][v][w]
__device__ float g_Wdt[3 * 64 * 64];          // [s][c][o]
__device__ float g_Wt9[9 * 64 * 64];          // [k][c][o]
__device__ float g_y[52428800u];              // pre-BN y; later reused for TCN z
__device__ float g_y2[52428800u];             // post BN1+residual+relu
__device__ float g_bnS[64u * 8192u];
__device__ float g_bnQ[64u * 8192u];
__device__ float g_stats[256];                // [off+c]=mean, [off+64+c]=rstd
__device__ float g_meanT[64 * 64 * 25];
__device__ float g_gs[64 * 25];               // 1+sigmoid spatial gate
__device__ float g_meanV[64 * 64 * 512];
__device__ float g_gt[64 * 512];              // 1+sigmoid temporal gate
__device__ float g_gc[64 * 64];               // 1+sigmoid channel gate

// ---------------- weight prep (transposes) ----------------
__global__ void k_prep(const float* __restrict__ Wd, const float* __restrict__ tw) {
    int tid = blockIdx.x * 256 + threadIdx.x;
    int stride = gridDim.x * 256;
    for (int i = tid; i < 3 * 64 * 64; i += stride) {
        int s = i / 4096, r = i % 4096, c = r / 64, o = r % 64;
        g_Wdt[i] = Wd[s * 4096 + o * 64 + c];
    }
    for (int i = tid; i < 9 * 64 * 64; i += stride) {
        int k = i / 4096, r = i % 4096, c = r / 64, o = r % 64;
        g_Wt9[i] = tw[o * 576 + c * 9 + k];
    }
}

// ---------------- fused fa/fb projection + Gram partials ----------------
// grid (64 n, 8 seg); 256 thr. Per block: 64 t's in 16 sub-chunks of 4 t.
// fab mapping: ig(8 row-groups of 4) x vq(8 v-quads) x tloc(4 t) = 256 threads.
// gram mapping: gv(32) x gw4(8*4) = 256 threads.
__global__ void __launch_bounds__(256) k_fabgram(
    const float* __restrict__ x, const float* __restrict__ Wa, const float* __restrict__ ba,
    const float* __restrict__ Wb, const float* __restrict__ bb)
{
    extern __shared__ float sm[];
    float* xs  = sm;                 // [c=64][4t*32v] = 8192
    float* Wab = sm + 8192;          // [s*32+r][stride65] = 6240
    float* fs  = sm + 8192 + 6240;   // [(s*2+side)][64k][32v] = 12288
    int n = blockIdx.x, seg = blockIdx.y, tid = threadIdx.x;
    int tseg0 = seg * 64;

    for (int idx = tid; idx < 3 * 32 * 64; idx += 256) {
        int s = idx / 2048, r = (idx / 64) % 32, c = idx % 64;
        float w = (r < 16) ? Wa[s * 1024 + r * 64 + c] : Wb[s * 1024 + (r - 16) * 64 + c];
        Wab[(s * 32 + r) * 65 + c] = w;
    }
    int ig = tid & 7;            // row group: rows ig*4..ig*4+3 (0..15 fa, 16..31 fb)
    int vq = (tid >> 3) & 7;     // v quad: v = vq*4..vq*4+3  (full 0..31 coverage)
    int tloc = tid >> 6;         // 0..3

    float bias[3][4];
#pragma unroll
    for (int s = 0; s < 3; s++)
#pragma unroll
        for (int j = 0; j < 4; j++) {
            int r = ig * 4 + j;
            bias[s][j] = (r < 16) ? ba[s * 16 + r] : bb[s * 16 + (r - 16)];
        }
    int side = ig >> 2;          // 0 -> fa, 1 -> fb
    int gv = tid >> 3, gw4 = (tid & 7) * 4;

    float gacc[3][4];
#pragma unroll
    for (int s = 0; s < 3; s++)
#pragma unroll
        for (int q = 0; q < 4; q++) gacc[s][q] = 0.f;

    for (int sub = 0; sub < 16; sub++) {
        int t0 = tseg0 + sub * 4;
        for (int idx = tid; idx < 8192; idx += 256) {
            int c = idx >> 7, r = idx & 127, t = r >> 5, v = r & 31;
            xs[idx] = (v < 25) ? x[(((size_t)n * 64 + c) * 512 + t0 + t) * 25 + v] : 0.f;
        }
        __syncthreads();
        // projection: full c reduction per thread
        float4 facc[3][4];
#pragma unroll
        for (int s = 0; s < 3; s++)
#pragma unroll
            for (int j = 0; j < 4; j++) {
                float b0 = bias[s][j];
                facc[s][j] = make_float4(b0, b0, b0, b0);
            }
        for (int c = 0; c < 64; c++) {
            float4 X = *(const float4*)&xs[c * 128 + tloc * 32 + vq * 4];
#pragma unroll
            for (int s = 0; s < 3; s++)
#pragma unroll
                for (int j = 0; j < 4; j++) {
                    float w = Wab[(s * 32 + ig * 4 + j) * 65 + c];
                    facc[s][j].x += w * X.x; facc[s][j].y += w * X.y;
                    facc[s][j].z += w * X.z; facc[s][j].w += w * X.w;
                }
        }
#pragma unroll
        for (int s = 0; s < 3; s++)
#pragma unroll
            for (int j = 0; j < 4; j++) {
                int kl = tloc * 16 + (ig & 3) * 4 + j;
                *(float4*)&fs[(s * 2 + side) * 2048 + kl * 32 + vq * 4] = facc[s][j];
            }
        __syncthreads();
        // gram accumulate over 64 k rows
#pragma unroll
        for (int s = 0; s < 3; s++) {
            const float* fap = &fs[(s * 2 + 0) * 2048];
            const float* fbp = &fs[(s * 2 + 1) * 2048];
            for (int kk = 0; kk < 64; kk++) {
                float fav = fap[kk * 32 + gv];
                float4 f4 = *(const float4*)&fbp[kk * 32 + gw4];
                gacc[s][0] += fav * f4.x; gacc[s][1] += fav * f4.y;
                gacc[s][2] += fav * f4.z; gacc[s][3] += fav * f4.w;
            }
        }
        __syncthreads();
    }
#pragma unroll
    for (int s = 0; s < 3; s++) {
        float* p = &g_Apart[((size_t)((n * 3 + s) * 8 + seg)) * 1024 + gv * 32 + gw4];
        p[0] = gacc[s][0]; p[1] = gacc[s][1]; p[2] = gacc[s][2]; p[3] = gacc[s][3];
    }
}

__global__ void k_gram2(const float* __restrict__ PA, const float* __restrict__ alpha) {
    int ns = blockIdx.x; int s = ns % 3;
    float al = alpha[0];
    for (int p = threadIdx.x; p < 625; p += 256) {
        int v = p / 25, w = p % 25;
        float sum = 0;
        for (int seg = 0; seg < 8; seg++)
            sum += g_Apart[((size_t)ns * 8 + seg) * 1024 + v * 32 + w];
        float A1 = tanhf(sum * (1.0f / 8192.0f));
        g_Aeff[ns * 625 + p] = PA[s * 625 + p] + al * A1;
    }
}

// ---------------- GCN + BN1 partial epilogue ----------------
#define ZST 112
__global__ void __launch_bounds__(256) k_gcn(const float* __restrict__ x) {
    extern __shared__ float sm[];
    float* xT = sm;                      // [t*25+v][stride 68 c]  6800
    float* zs = sm + 6800;               // [c][tw stride 112]     7168
    float* wd = sm + 6800 + 7168;        // [c][o]                 4096
    float* ae = sm + 6800 + 7168 + 4096; // [v][w stride 28]       700
    int tcb = blockIdx.x, n = blockIdx.y;
    int t0 = tcb * 4, tid = threadIdx.x;

    for (int idx = tid; idx < 6400; idx += 256) {
        int c = idx / 100, r = idx % 100, t = r / 25, v = r % 25;
        xT[(t * 25 + v) * 68 + c] = x[(((size_t)n * 64 + c) * 512 + t0 + t) * 25 + v];
    }
    int cg = tid >> 4, tg2 = tid & 15;
    int zt[7], zw[7];
#pragma unroll
    for (int j = 0; j < 7; j++) { int tw = tg2 + 16 * j; zt[j] = tw / 28; zw[j] = tw % 28; }
    int ot = tid & 15, twt = tid >> 4;
    int gt_[7], gw[7];
#pragma unroll
    for (int j = 0; j < 7; j++) { int tw = twt + 16 * j; gt_[j] = tw / 28; gw[j] = tw % 28; }

    float acc[4][7];
#pragma unroll
    for (int i = 0; i < 4; i++)
#pragma unroll
        for (int j = 0; j < 7; j++) acc[i][j] = 0.f;

    for (int s = 0; s < 3; s++) {
        for (int idx = tid; idx < 700; idx += 256) {
            int v = idx / 28, w = idx % 28;
            ae[idx] = (w < 25) ? g_Aeff[(size_t)(n * 3 + s) * 625 + v * 25 + w] : 0.f;
        }
        for (int idx = tid; idx < 4096; idx += 256) wd[idx] = g_Wdt[s * 4096 + idx];
        __syncthreads();
        {
            float tmp[4][7];
#pragma unroll
            for (int i = 0; i < 4; i++)
#pragma unroll
                for (int j = 0; j < 7; j++) tmp[i][j] = 0.f;
            for (int v = 0; v < 25; v++) {
#pragma unroll
                for (int j = 0; j < 7; j++) {
                    float4 X = *(const float4*)&xT[(zt[j] * 25 + v) * 68 + 4 * cg];
                    float a = ae[v * 28 + zw[j]];
                    tmp[0][j] += X.x * a; tmp[1][j] += X.y * a;
                    tmp[2][j] += X.z * a; tmp[3][j] += X.w * a;
                }
            }
#pragma unroll
            for (int i = 0; i < 4; i++)
#pragma unroll
                for (int j = 0; j < 7; j++)
                    zs[(4 * cg + i) * ZST + tg2 + 16 * j] = tmp[i][j];
        }
        __syncthreads();
        for (int c = 0; c < 64; c++) {
            float4 w4 = *(const float4*)&wd[c * 64 + 4 * ot];
#pragma unroll
            for (int j = 0; j < 7; j++) {
                float z = zs[c * ZST + twt + 16 * j];
                acc[0][j] += w4.x * z; acc[1][j] += w4.y * z;
                acc[2][j] += w4.z * z; acc[3][j] += w4.w * z;
            }
        }
        __syncthreads();
    }
#pragma unroll
    for (int j = 0; j < 7; j++) {
        if (gw[j] < 25) {
#pragma unroll
            for (int i = 0; i < 4; i++)
                g_y[(((size_t)n * 64 + 4 * ot + i) * 512 + t0 + gt_[j]) * 25 + gw[j]] = acc[i][j];
        }
    }
    // BN1 partials: padded-w acc slots are exactly 0 (Ae padded to 0) so include all j
#pragma unroll
    for (int i = 0; i < 4; i++) {
        float a = 0, b = 0;
#pragma unroll
        for (int j = 0; j < 7; j++) { a += acc[i][j]; b += acc[i][j] * acc[i][j]; }
        zs[(4 * ot + i) * 16 + twt] = a;
        zs[1792 + (4 * ot + i) * 16 + twt] = b;
    }
    __syncthreads();
    if (tid < 64) {
        float a = 0, b = 0;
        for (int p = 0; p < 16; p++) { a += zs[tid * 16 + p]; b += zs[1792 + tid * 16 + p]; }
        g_bnS[(size_t)tid * 8192 + n * 128 + tcb] = a;
        g_bnQ[(size_t)tid * 8192 + n * 128 + tcb] = b;
    }
}

__global__ void k_bnfin(int cnt, int off) {
    __shared__ float s1[256], s2[256];
    int c = blockIdx.x, tid = threadIdx.x;
    float a = 0, b = 0;
    for (int i = tid; i < cnt; i += 256) {
        a += g_bnS[(size_t)c * 8192 + i];
        b += g_bnQ[(size_t)c * 8192 + i];
    }
    s1[tid] = a; s2[tid] = b; __syncthreads();
    for (int st = 128; st > 0; st >>= 1) {
        if (tid < st) { s1[tid] += s1[tid + st]; s2[tid] += s2[tid + st]; }
        __syncthreads();
    }
    if (tid == 0) {
        float m = s1[0] / 819200.0f;
        float v = s2[0] / 819200.0f - m * m;
        g_stats[off + c] = m;
        g_stats[off + 64 + c] = rsqrtf(v + 1e-5f);
    }
}

// BN1 apply + residual + relu -> g_y2, fused T-mean partials -> g_meanT
__global__ void __launch_bounds__(256) k_bnapply_mt(
    const float* __restrict__ gm, const float* __restrict__ bt, const float* __restrict__ x)
{
    __shared__ float red[8 * 33];
    int nc = blockIdx.x, tid = threadIdx.x, lane = tid & 31, tg = tid >> 5;
    int c = nc & 63;
    float m = g_stats[c], r = g_stats[64 + c];
    float sc = r * gm[c], sb = bt[c] - m * sc;
    float a = 0;
    if (lane < 25) {
        size_t base = (size_t)nc * 12800 + lane;
        for (int t = tg; t < 512; t += 8) {
            float y = g_y[base + t * 25];
            float o = fmaxf(y * sc + sb + x[base + t * 25], 0.f);
            g_y2[base + t * 25] = o;
            a += o;
        }
        red[tg * 33 + lane] = a;
    }
    __syncthreads();
    if (tid < 25) {
        float s = 0;
        for (int g = 0; g < 8; g++) s += red[g * 33 + tid];
        g_meanT[nc * 25 + tid] = s * (1.f / 512.f);
    }
}

// ---------------- attention chain ----------------
__global__ void k_sattn(const float* __restrict__ saw, const float* __restrict__ sab) {
    int n = blockIdx.x, v = threadIdx.x;
    if (v < 25) {
        float acc = sab[0];
        for (int c = 0; c < 64; c++) {
            const float* m = &g_meanT[(n * 64 + c) * 25];
            const float* w = &saw[c * 25];
#pragma unroll
            for (int j = 0; j < 25; j++) {
                int vv = v + j - 12;
                if (vv >= 0 && vv < 25) acc += w[j] * m[vv];
            }
        }
        g_gs[n * 25 + v] = 1.f + 1.f / (1.f + expf(-acc));
    }
}

__global__ void __launch_bounds__(256) k_meanV() {
    __shared__ float sgs[25];
    int nc = blockIdx.x, tid = threadIdx.x;
    int n = nc >> 6;
    if (tid < 25) sgs[tid] = g_gs[n * 25 + tid];
    __syncthreads();
    for (int t = tid; t < 512; t += 256) {
        const float* row = &g_y2[(size_t)nc * 12800 + t * 25];
        float a = 0;
#pragma unroll
        for (int v = 0; v < 25; v++) a += row[v] * sgs[v];
        g_meanV[nc * 512 + t] = a * (1.f / 25.f);
    }
}

__global__ void k_tattn(const float* __restrict__ taw, const float* __restrict__ tab) {
    int n = blockIdx.x, tid = threadIdx.x;
    for (int t = tid; t < 512; t += 256) {
        float acc = tab[0];
        for (int c = 0; c < 64; c++) {
            const float* m = &g_meanV[(n * 64 + c) * 512];
            const float* w = &taw[c * 9];
#pragma unroll
            for (int j = 0; j < 9; j++) {
                int tt = t + j - 4;
                if (tt >= 0 && tt < 512) acc += w[j] * m[tt];
            }
        }
        g_gt[n * 512 + t] = 1.f + 1.f / (1.f + expf(-acc));
    }
}

__global__ void k_cse(const float* __restrict__ f1w, const float* __restrict__ f1b,
                      const float* __restrict__ f2w, const float* __restrict__ f2b) {
    __shared__ float sm3[64], sh[32];
    int n = blockIdx.x, c = threadIdx.x;
    const float* m = &g_meanV[(n * 64 + c) * 512];
    const float* gt = &g_gt[n * 512];
    float a = 0;
    for (int t = 0; t < 512; t++) a += m[t] * gt[t];
    sm3[c] = a * (1.f / 512.f);
    __syncthreads();
    if (c < 32) {
        float h = f1b[c];
        for (int k = 0; k < 64; k++) h += f1w[c * 64 + k] * sm3[k];
        sh[c] = fmaxf(h, 0.f);
    }
    __syncthreads();
    float o = f2b[c];
    for (int j = 0; j < 32; j++) o += f2w[c * 32 + j] * sh[j];
    g_gc[n * 64 + c] = 1.f + 1.f / (1.f + expf(-o));
}

// ---------------- TCN (8-t chunks, 512 thr) + BN2 partial epilogue ----------------
__global__ void __launch_bounds__(512) k_tcn() {
    extern __shared__ float sm[];
    float* yin = sm;          // [c=64][16*28] = 28672
    float* wk = sm + 28672;   // 4096; first reused for gate staging
    int tcb = blockIdx.x, n = blockIdx.y;
    int t0 = tcb * 8, tid = threadIdx.x;

    if (tid < 25) wk[tid] = g_gs[n * 25 + tid];
    if (tid >= 32 && tid < 48) {
        int tl = tid - 32, tin = t0 - 4 + tl;
        wk[tid] = (tin >= 0 && tin < 512) ? g_gt[n * 512 + tin] : 0.f;
    }
    if (tid >= 64 && tid < 128) wk[tid] = g_gc[n * 64 + (tid - 64)];
    __syncthreads();

    for (int idx = tid; idx < 28672; idx += 512) {
        int c = idx / 448, r = idx % 448, tl = r / 28, w = r % 28;
        int tin = t0 - 4 + tl;
        float val = 0.f;
        if (w < 25 && tin >= 0 && tin < 512) {
            val = g_y2[(((size_t)n * 64 + c) * 512 + tin) * 25 + w]
                * wk[w] * wk[32 + tl] * wk[64 + c];
        }
        yin[idx] = val;
    }

    int ot = tid & 15, twt = tid >> 4;
    float acc[4][7];
#pragma unroll
    for (int i = 0; i < 4; i++)
#pragma unroll
        for (int j = 0; j < 7; j++) acc[i][j] = 0.f;

    for (int k = 0; k < 9; k++) {
        __syncthreads();
        for (int idx = tid; idx < 4096; idx += 512) wk[idx] = g_Wt9[k * 4096 + idx];
        __syncthreads();
        for (int c = 0; c < 64; c++) {
            float4 w4 = *(const float4*)&wk[c * 64 + 4 * ot];
            const float* yr = &yin[c * 448 + 28 * k];
#pragma unroll
            for (int j = 0; j < 7; j++) {
                float z = yr[twt + 32 * j];
                acc[0][j] += w4.x * z; acc[1][j] += w4.y * z;
                acc[2][j] += w4.z * z; acc[3][j] += w4.w * z;
            }
        }
    }
#pragma unroll
    for (int j = 0; j < 7; j++) {
        int slot = twt + 32 * j, tj = slot / 28, wj = slot % 28;
        if (wj < 25) {
#pragma unroll
            for (int i = 0; i < 4; i++)
                g_y[(((size_t)n * 64 + 4 * ot + i) * 512 + t0 + tj) * 25 + wj] = acc[i][j];
        }
    }
    // BN2 partials (padded-w slots are exactly 0: yin padded to 0)
    __syncthreads();
#pragma unroll
    for (int i = 0; i < 4; i++) {
        float a = 0, b = 0;
#pragma unroll
        for (int j = 0; j < 7; j++) { a += acc[i][j]; b += acc[i][j] * acc[i][j]; }
        wk[(4 * ot + i) * 32 + twt] = a;
        wk[2048 + (4 * ot + i) * 32 + twt] = b;
    }
    __syncthreads();
    if (tid < 64) {
        float a = 0, b = 0;
        for (int p = 0; p < 32; p++) { a += wk[tid * 32 + p]; b += wk[2048 + tid * 32 + p]; }
        g_bnS[(size_t)tid * 8192 + n * 64 + tcb] = a;
        g_bnQ[(size_t)tid * 8192 + n * 64 + tcb] = b;
    }
}

// final: out = relu(bn2(g_y) + x), vectorized
__global__ void __launch_bounds__(256) k_bnapply2(
    const float* __restrict__ gm, const float* __restrict__ bt,
    const float* __restrict__ x, float* __restrict__ out)
{
    size_t i4 = (size_t)blockIdx.x * 256 + threadIdx.x;
    size_t flat = i4 * 4;
    int c = (int)((flat / 12800) % 64);
    float m = g_stats[128 + c], r = g_stats[192 + c];
    float sc = r * gm[c];
    float sb = bt[c] - m * sc;
    float4 Y = *(const float4*)&g_y[flat];
    float4 X = *(const float4*)&x[flat];
    float4 O;
    O.x = fmaxf(Y.x * sc + sb + X.x, 0.f);
    O.y = fmaxf(Y.y * sc + sb + X.y, 0.f);
    O.z = fmaxf(Y.z * sc + sb + X.z, 0.f);
    O.w = fmaxf(Y.w * sc + sb + X.w, 0.f);
    *(float4*)&out[flat] = O;
}

// ---------------- launcher ----------------
extern "C" void kernel_launch(void* const* d_in, const int* in_sizes, int n_in,
                              void* d_out, int out_size) {
    const float* x   = (const float*)d_in[0];
    const float* PA  = (const float*)d_in[1];
    const float* alp = (const float*)d_in[2];
    const float* Wa  = (const float*)d_in[3];
    const float* ba  = (const float*)d_in[4];
    const float* Wb  = (const float*)d_in[5];
    const float* bb  = (const float*)d_in[6];
    const float* Wd  = (const float*)d_in[7];
    const float* bng = (const float*)d_in[9];
    const float* bnb = (const float*)d_in[10];
    const float* saw = (const float*)d_in[11];
    const float* sab = (const float*)d_in[12];
    const float* taw = (const float*)d_in[13];
    const float* tab = (const float*)d_in[14];
    const float* f1w = (const float*)d_in[15];
    const float* f1b = (const float*)d_in[16];
    const float* f2w = (const float*)d_in[17];
    const float* f2b = (const float*)d_in[18];
    const float* tw  = (const float*)d_in[19];
    const float* tbg = (const float*)d_in[21];
    const float* tbb = (const float*)d_in[22];
    float* out = (float*)d_out;

    cudaFuncSetAttribute(k_fabgram, cudaFuncAttributeMaxDynamicSharedMemorySize, 106880);
    cudaFuncSetAttribute(k_gcn, cudaFuncAttributeMaxDynamicSharedMemorySize, 75056);
    cudaFuncSetAttribute(k_tcn, cudaFuncAttributeMaxDynamicSharedMemorySize, 131072);

    k_prep<<<32, 256>>>(Wd, tw);
    k_fabgram<<<dim3(64, 8), 256, 106880>>>(x, Wa, ba, Wb, bb);
    k_gram2<<<192, 256>>>(PA, alp);
    k_gcn<<<dim3(128, 64), 256, 75056>>>(x);
    k_bnfin<<<64, 256>>>(8192, 0);
    k_bnapply_mt<<<4096, 256>>>(bng, bnb, x);
    k_sattn<<<64, 32>>>(saw, sab);
    k_meanV<<<4096, 256>>>();
    k_tattn<<<64, 256>>>(taw, tab);
    k_cse<<<64, 64>>>(f1w, f1b, f2w, f2b);
    k_tcn<<<dim3(64, 64), 512, 131072>>>();
    k_bnfin<<<64, 256>>>(4096, 128);
    k_bnapply2<<<51200, 256>>>(tbg, tbb, x, out);
}

// round 5
// speedup vs baseline: 1.1843x; 1.1840x over previous
#include <cuda_runtime.h>
#include <cuda_bf16.h>
#include <math.h>

// dims: N=64, C=64, T=512, V=25, S=3, I=16
// ---------------- device scratch (no cudaMalloc allowed) ----------------
__device__ float g_Apart[1536u * 1024u];      // [(n*3+s)*8+seg][v32*32]
__device__ float g_Aeff[192 * 625];           // [n*3+s][v][w]
__device__ float g_Wdt[3 * 64 * 64];          // [s][c][o]
__device__ __nv_bfloat16 g_Wt9h[9 * 64 * 72]; // [k][c][o pad72] bf16 hi
__device__ __nv_bfloat16 g_Wt9l[9 * 64 * 72]; // bf16 lo
__device__ float g_y[52428800u];              // pre-BN y; later reused for TCN z
__device__ float g_y2[52428800u];             // post BN1+residual+relu
__device__ float g_bnS[64u * 8192u];
__device__ float g_bnQ[64u * 8192u];
__device__ float g_stats[256];                // [off+c]=mean, [off+64+c]=rstd
__device__ float g_meanT[64 * 64 * 25];
__device__ float g_gs[64 * 25];               // 1+sigmoid spatial gate
__device__ float g_meanV[64 * 64 * 512];
__device__ float g_gt[64 * 512];              // 1+sigmoid temporal gate
__device__ float g_gc[64 * 64];               // 1+sigmoid channel gate

// ---------------- mma helpers ----------------
__device__ __forceinline__ unsigned su32(const void* p) {
    return (unsigned)__cvta_generic_to_shared(p);
}
__device__ __forceinline__ void ldsm4(unsigned addr, unsigned* r) {
    asm volatile("ldmatrix.sync.aligned.m8n8.x4.shared.b16 {%0,%1,%2,%3}, [%4];"
                 : "=r"(r[0]), "=r"(r[1]), "=r"(r[2]), "=r"(r[3]) : "r"(addr));
}
__device__ __forceinline__ void ldsm4t(unsigned addr, unsigned* r) {
    asm volatile("ldmatrix.sync.aligned.m8n8.x4.trans.shared.b16 {%0,%1,%2,%3}, [%4];"
                 : "=r"(r[0]), "=r"(r[1]), "=r"(r[2]), "=r"(r[3]) : "r"(addr));
}
__device__ __forceinline__ void mma16816(float* d, const unsigned* a, const unsigned* b) {
    asm volatile("mma.sync.aligned.m16n8k16.row.col.f32.bf16.bf16.f32 "
                 "{%0,%1,%2,%3}, {%4,%5,%6,%7}, {%8,%9}, {%0,%1,%2,%3};"
                 : "+f"(d[0]), "+f"(d[1]), "+f"(d[2]), "+f"(d[3])
                 : "r"(a[0]), "r"(a[1]), "r"(a[2]), "r"(a[3]), "r"(b[0]), "r"(b[1]));
}

// ---------------- weight prep ----------------
__global__ void k_prep(const float* __restrict__ Wd, const float* __restrict__ tw) {
    int tid = blockIdx.x * 256 + threadIdx.x;
    int stride = gridDim.x * 256;
    for (int i = tid; i < 3 * 64 * 64; i += stride) {
        int s = i / 4096, r = i % 4096, c = r / 64, o = r % 64;
        g_Wdt[i] = Wd[s * 4096 + o * 64 + c];
    }
    // bf16 split TCN weights: [k][c][o pad 72]
    for (int i = tid; i < 9 * 64 * 72; i += stride) {
        int k = i / 4608, r = i % 4608, c = r / 72, o = r % 72;
        float w = (o < 64) ? tw[o * 576 + c * 9 + k] : 0.f;
        __nv_bfloat16 h = __float2bfloat16(w);
        g_Wt9h[i] = h;
        g_Wt9l[i] = __float2bfloat16(w - __bfloat162float(h));
    }
}

// ---------------- fused fa/fb projection + Gram partials ----------------
__global__ void __launch_bounds__(256) k_fabgram(
    const float* __restrict__ x, const float* __restrict__ Wa, const float* __restrict__ ba,
    const float* __restrict__ Wb, const float* __restrict__ bb)
{
    extern __shared__ float sm[];
    float* xs  = sm;                 // [c=64][4t*32v] = 8192
    float* Wab = sm + 8192;          // [s*32+r][stride65] = 6240
    float* fs  = sm + 8192 + 6240;   // [(s*2+side)][64k][32v] = 12288
    int n = blockIdx.x, seg = blockIdx.y, tid = threadIdx.x;
    int tseg0 = seg * 64;

    for (int idx = tid; idx < 3 * 32 * 64; idx += 256) {
        int s = idx / 2048, r = (idx / 64) % 32, c = idx % 64;
        float w = (r < 16) ? Wa[s * 1024 + r * 64 + c] : Wb[s * 1024 + (r - 16) * 64 + c];
        Wab[(s * 32 + r) * 65 + c] = w;
    }
    int ig = tid & 7;
    int vq = (tid >> 3) & 7;
    int tloc = tid >> 6;

    float bias[3][4];
#pragma unroll
    for (int s = 0; s < 3; s++)
#pragma unroll
        for (int j = 0; j < 4; j++) {
            int r = ig * 4 + j;
            bias[s][j] = (r < 16) ? ba[s * 16 + r] : bb[s * 16 + (r - 16)];
        }
    int side = ig >> 2;
    int gv = tid >> 3, gw4 = (tid & 7) * 4;

    float gacc[3][4];
#pragma unroll
    for (int s = 0; s < 3; s++)
#pragma unroll
        for (int q = 0; q < 4; q++) gacc[s][q] = 0.f;

    for (int sub = 0; sub < 16; sub++) {
        int t0 = tseg0 + sub * 4;
        for (int idx = tid; idx < 8192; idx += 256) {
            int c = idx >> 7, r = idx & 127, t = r >> 5, v = r & 31;
            xs[idx] = (v < 25) ? x[(((size_t)n * 64 + c) * 512 + t0 + t) * 25 + v] : 0.f;
        }
        __syncthreads();
        float4 facc[3][4];
#pragma unroll
        for (int s = 0; s < 3; s++)
#pragma unroll
            for (int j = 0; j < 4; j++) {
                float b0 = bias[s][j];
                facc[s][j] = make_float4(b0, b0, b0, b0);
            }
        for (int c = 0; c < 64; c++) {
            float4 X = *(const float4*)&xs[c * 128 + tloc * 32 + vq * 4];
#pragma unroll
            for (int s = 0; s < 3; s++)
#pragma unroll
                for (int j = 0; j < 4; j++) {
                    float w = Wab[(s * 32 + ig * 4 + j) * 65 + c];
                    facc[s][j].x += w * X.x; facc[s][j].y += w * X.y;
                    facc[s][j].z += w * X.z; facc[s][j].w += w * X.w;
                }
        }
#pragma unroll
        for (int s = 0; s < 3; s++)
#pragma unroll
            for (int j = 0; j < 4; j++) {
                int kl = tloc * 16 + (ig & 3) * 4 + j;
                *(float4*)&fs[(s * 2 + side) * 2048 + kl * 32 + vq * 4] = facc[s][j];
            }
        __syncthreads();
#pragma unroll
        for (int s = 0; s < 3; s++) {
            const float* fap = &fs[(s * 2 + 0) * 2048];
            const float* fbp = &fs[(s * 2 + 1) * 2048];
            for (int kk = 0; kk < 64; kk++) {
                float fav = fap[kk * 32 + gv];
                float4 f4 = *(const float4*)&fbp[kk * 32 + gw4];
                gacc[s][0] += fav * f4.x; gacc[s][1] += fav * f4.y;
                gacc[s][2] += fav * f4.z; gacc[s][3] += fav * f4.w;
            }
        }
        __syncthreads();
    }
#pragma unroll
    for (int s = 0; s < 3; s++) {
        float* p = &g_Apart[((size_t)((n * 3 + s) * 8 + seg)) * 1024 + gv * 32 + gw4];
        p[0] = gacc[s][0]; p[1] = gacc[s][1]; p[2] = gacc[s][2]; p[3] = gacc[s][3];
    }
}

__global__ void k_gram2(const float* __restrict__ PA, const float* __restrict__ alpha) {
    int ns = blockIdx.x; int s = ns % 3;
    float al = alpha[0];
    for (int p = threadIdx.x; p < 625; p += 256) {
        int v = p / 25, w = p % 25;
        float sum = 0;
        for (int seg = 0; seg < 8; seg++)
            sum += g_Apart[((size_t)ns * 8 + seg) * 1024 + v * 32 + w];
        float A1 = tanhf(sum * (1.0f / 8192.0f));
        g_Aeff[ns * 625 + p] = PA[s * 625 + p] + al * A1;
    }
}

// ---------------- GCN + BN1 partial epilogue ----------------
#define ZST 112
__global__ void __launch_bounds__(256) k_gcn(const float* __restrict__ x) {
    extern __shared__ float sm[];
    float* xT = sm;                      // [t*25+v][stride 68 c]  6800
    float* zs = sm + 6800;               // [c][tw stride 112]     7168
    float* wd = sm + 6800 + 7168;        // [c][o]                 4096
    float* ae = sm + 6800 + 7168 + 4096; // [v][w stride 28]       700
    int tcb = blockIdx.x, n = blockIdx.y;
    int t0 = tcb * 4, tid = threadIdx.x;

    for (int idx = tid; idx < 6400; idx += 256) {
        int c = idx / 100, r = idx % 100, t = r / 25, v = r % 25;
        xT[(t * 25 + v) * 68 + c] = x[(((size_t)n * 64 + c) * 512 + t0 + t) * 25 + v];
    }
    int cg = tid >> 4, tg2 = tid & 15;
    int zt[7], zw[7];
#pragma unroll
    for (int j = 0; j < 7; j++) { int tw = tg2 + 16 * j; zt[j] = tw / 28; zw[j] = tw % 28; }
    int ot = tid & 15, twt = tid >> 4;
    int gt_[7], gw[7];
#pragma unroll
    for (int j = 0; j < 7; j++) { int tw = twt + 16 * j; gt_[j] = tw / 28; gw[j] = tw % 28; }

    float acc[4][7];
#pragma unroll
    for (int i = 0; i < 4; i++)
#pragma unroll
        for (int j = 0; j < 7; j++) acc[i][j] = 0.f;

    for (int s = 0; s < 3; s++) {
        for (int idx = tid; idx < 700; idx += 256) {
            int v = idx / 28, w = idx % 28;
            ae[idx] = (w < 25) ? g_Aeff[(size_t)(n * 3 + s) * 625 + v * 25 + w] : 0.f;
        }
        for (int idx = tid; idx < 4096; idx += 256) wd[idx] = g_Wdt[s * 4096 + idx];
        __syncthreads();
        {
            float tmp[4][7];
#pragma unroll
            for (int i = 0; i < 4; i++)
#pragma unroll
                for (int j = 0; j < 7; j++) tmp[i][j] = 0.f;
            for (int v = 0; v < 25; v++) {
#pragma unroll
                for (int j = 0; j < 7; j++) {
                    float4 X = *(const float4*)&xT[(zt[j] * 25 + v) * 68 + 4 * cg];
                    float a = ae[v * 28 + zw[j]];
                    tmp[0][j] += X.x * a; tmp[1][j] += X.y * a;
                    tmp[2][j] += X.z * a; tmp[3][j] += X.w * a;
                }
            }
#pragma unroll
            for (int i = 0; i < 4; i++)
#pragma unroll
                for (int j = 0; j < 7; j++)
                    zs[(4 * cg + i) * ZST + tg2 + 16 * j] = tmp[i][j];
        }
        __syncthreads();
        for (int c = 0; c < 64; c++) {
            float4 w4 = *(const float4*)&wd[c * 64 + 4 * ot];
#pragma unroll
            for (int j = 0; j < 7; j++) {
                float z = zs[c * ZST + twt + 16 * j];
                acc[0][j] += w4.x * z; acc[1][j] += w4.y * z;
                acc[2][j] += w4.z * z; acc[3][j] += w4.w * z;
            }
        }
        __syncthreads();
    }
#pragma unroll
    for (int j = 0; j < 7; j++) {
        if (gw[j] < 25) {
#pragma unroll
            for (int i = 0; i < 4; i++)
                g_y[(((size_t)n * 64 + 4 * ot + i) * 512 + t0 + gt_[j]) * 25 + gw[j]] = acc[i][j];
        }
    }
#pragma unroll
    for (int i = 0; i < 4; i++) {
        float a = 0, b = 0;
#pragma unroll
        for (int j = 0; j < 7; j++) { a += acc[i][j]; b += acc[i][j] * acc[i][j]; }
        zs[(4 * ot + i) * 16 + twt] = a;
        zs[1792 + (4 * ot + i) * 16 + twt] = b;
    }
    __syncthreads();
    if (tid < 64) {
        float a = 0, b = 0;
        for (int p = 0; p < 16; p++) { a += zs[tid * 16 + p]; b += zs[1792 + tid * 16 + p]; }
        g_bnS[(size_t)tid * 8192 + n * 128 + tcb] = a;
        g_bnQ[(size_t)tid * 8192 + n * 128 + tcb] = b;
    }
}

__global__ void k_bnfin(int cnt, int off) {
    __shared__ float s1[256], s2[256];
    int c = blockIdx.x, tid = threadIdx.x;
    float a = 0, b = 0;
    for (int i = tid; i < cnt; i += 256) {
        a += g_bnS[(size_t)c * 8192 + i];
        b += g_bnQ[(size_t)c * 8192 + i];
    }
    s1[tid] = a; s2[tid] = b; __syncthreads();
    for (int st = 128; st > 0; st >>= 1) {
        if (tid < st) { s1[tid] += s1[tid + st]; s2[tid] += s2[tid + st]; }
        __syncthreads();
    }
    if (tid == 0) {
        float m = s1[0] / 819200.0f;
        float v = s2[0] / 819200.0f - m * m;
        g_stats[off + c] = m;
        g_stats[off + 64 + c] = rsqrtf(v + 1e-5f);
    }
}

// BN1 apply + residual + relu -> g_y2, fused T-mean partials -> g_meanT
__global__ void __launch_bounds__(256) k_bnapply_mt(
    const float* __restrict__ gm, const float* __restrict__ bt, const float* __restrict__ x)
{
    __shared__ float red[8 * 33];
    int nc = blockIdx.x, tid = threadIdx.x, lane = tid & 31, tg = tid >> 5;
    int c = nc & 63;
    float m = g_stats[c], r = g_stats[64 + c];
    float sc = r * gm[c], sb = bt[c] - m * sc;
    float a = 0;
    if (lane < 25) {
        size_t base = (size_t)nc * 12800 + lane;
        for (int t = tg; t < 512; t += 8) {
            float y = g_y[base + t * 25];
            float o = fmaxf(y * sc + sb + x[base + t * 25], 0.f);
            g_y2[base + t * 25] = o;
            a += o;
        }
        red[tg * 33 + lane] = a;
    }
    __syncthreads();
    if (tid < 25) {
        float s = 0;
        for (int g = 0; g < 8; g++) s += red[g * 33 + tid];
        g_meanT[nc * 25 + tid] = s * (1.f / 512.f);
    }
}

// ---------------- attention chain ----------------
__global__ void k_sattn(const float* __restrict__ saw, const float* __restrict__ sab) {
    int n = blockIdx.x, v = threadIdx.x;
    if (v < 25) {
        float acc = sab[0];
        for (int c = 0; c < 64; c++) {
            const float* m = &g_meanT[(n * 64 + c) * 25];
            const float* w = &saw[c * 25];
#pragma unroll
            for (int j = 0; j < 25; j++) {
                int vv = v + j - 12;
                if (vv >= 0 && vv < 25) acc += w[j] * m[vv];
            }
        }
        g_gs[n * 25 + v] = 1.f + 1.f / (1.f + expf(-acc));
    }
}

__global__ void __launch_bounds__(256) k_meanV() {
    __shared__ float sgs[25];
    int nc = blockIdx.x, tid = threadIdx.x;
    int n = nc >> 6;
    if (tid < 25) sgs[tid] = g_gs[n * 25 + tid];
    __syncthreads();
    for (int t = tid; t < 512; t += 256) {
        const float* row = &g_y2[(size_t)nc * 12800 + t * 25];
        float a = 0;
#pragma unroll
        for (int v = 0; v < 25; v++) a += row[v] * sgs[v];
        g_meanV[nc * 512 + t] = a * (1.f / 25.f);
    }
}

__global__ void k_tattn(const float* __restrict__ taw, const float* __restrict__ tab) {
    int n = blockIdx.x, tid = threadIdx.x;
    for (int t = tid; t < 512; t += 256) {
        float acc = tab[0];
        for (int c = 0; c < 64; c++) {
            const float* m = &g_meanV[(n * 64 + c) * 512];
            const float* w = &taw[c * 9];
#pragma unroll
            for (int j = 0; j < 9; j++) {
                int tt = t + j - 4;
                if (tt >= 0 && tt < 512) acc += w[j] * m[tt];
            }
        }
        g_gt[n * 512 + t] = 1.f + 1.f / (1.f + expf(-acc));
    }
}

__global__ void k_cse(const float* __restrict__ f1w, const float* __restrict__ f1b,
                      const float* __restrict__ f2w, const float* __restrict__ f2b) {
    __shared__ float sm3[64], sh[32];
    int n = blockIdx.x, c = threadIdx.x;
    const float* m = &g_meanV[(n * 64 + c) * 512];
    const float* gt = &g_gt[n * 512];
    float a = 0;
    for (int t = 0; t < 512; t++) a += m[t] * gt[t];
    sm3[c] = a * (1.f / 512.f);
    __syncthreads();
    if (c < 32) {
        float h = f1b[c];
        for (int k = 0; k < 64; k++) h += f1w[c * 64 + k] * sm3[k];
        sh[c] = fmaxf(h, 0.f);
    }
    __syncthreads();
    float o = f2b[c];
    for (int j = 0; j < 32; j++) o += f2w[c * 32 + j] * sh[j];
    g_gc[n * 64 + c] = 1.f + 1.f / (1.f + expf(-o));
}

// ---------------- TCN via mma.sync bf16-split + BN2 partial epilogue ----------------
// Per block (tcb, n): 8 t's -> 200 output slots (M pad 208), N=64 o, K = 64c x 9 taps.
// A[s][c] bf16 hi/lo, s in [0,408) = flattened (t,v) incl halo; row stride 72 (144B).
#define TCN_SMEM 189440
__global__ void __launch_bounds__(512) k_tcn() {
    extern __shared__ char smemraw[];
    __nv_bfloat16* Ah = (__nv_bfloat16*)smemraw;                 // [408][72]
    __nv_bfloat16* Wh = (__nv_bfloat16*)(smemraw + 117504);      // [64][72]
    __nv_bfloat16* Wl = (__nv_bfloat16*)(smemraw + 126720);
    float* zout = (float*)(smemraw + 135936);                    // [64][209]
    __shared__ float gsg[25], gtg[17], gcg[64];
    int tcb = blockIdx.x, n = blockIdx.y;
    int t0 = tcb * 8, tid = threadIdx.x;
    int wid = tid >> 5, lane = tid & 31;

    if (tid < 25) gsg[tid] = g_gs[n * 25 + tid];
    if (tid >= 32 && tid < 49) {
        int tin = t0 - 4 + (tid - 32);
        gtg[tid - 32] = (tin >= 0 && tin < 512) ? g_gt[n * 512 + tin] : 0.f;
    }
    if (tid >= 64 && tid < 128) gcg[tid - 64] = g_gc[n * 64 + (tid - 64)];
    __syncthreads();

    // stage gated A, bf16 split (hi at Ah, lo at Ah + 58752 bytes)
    for (int idx = tid; idx < 408 * 64; idx += 512) {
        int c = idx / 408, s = idx - c * 408;
        int tvg = (t0 - 4) * 25 + s;
        float val = 0.f;
        if (tvg >= 0 && tvg < 12800)
            val = g_y2[(size_t)(n * 64 + c) * 12800 + tvg] * gsg[s % 25] * gtg[s / 25] * gcg[c];
        __nv_bfloat16 h = __float2bfloat16(val);
        Ah[s * 72 + c] = h;
        Ah[29376 + s * 72 + c] = __float2bfloat16(val - __bfloat162float(h)); // lo region (+58752B)
    }

    // tile assignment: 52 = 13 m-tiles x 4 n16 groups
    int mt[4], nb[4], cnt = 0;
    for (int tl = wid; tl < 52; tl += 16) { mt[cnt] = tl % 13; nb[cnt] = (tl / 13) * 16; cnt++; }
    float acc[4][8];
#pragma unroll
    for (int q = 0; q < 4; q++)
#pragma unroll
        for (int i = 0; i < 8; i++) acc[q][i] = 0.f;

    unsigned baseA = su32(Ah), baseW = su32(Wh);
    int arow = lane & 15, acol8 = (lane >> 4) << 3;

    for (int tap = 0; tap < 9; tap++) {
        __syncthreads();
        for (int idx = tid; idx < 4608; idx += 512) {
            Wh[idx] = g_Wt9h[tap * 4608 + idx];
            Wl[idx] = g_Wt9l[tap * 4608 + idx];
        }
        __syncthreads();
#pragma unroll
        for (int q = 0; q < 4; q++) {
            if (q >= cnt) break;
            int rb = mt[q] * 16 + 25 * tap;
#pragma unroll
            for (int ks = 0; ks < 4; ks++) {
                int c0 = ks * 16;
                unsigned aaddr = baseA + (unsigned)(((rb + arow) * 72 + c0 + acol8) * 2);
                unsigned ah[4], al[4], bh[4], bl[4];
                ldsm4(aaddr, ah);
                ldsm4(aaddr + 58752u, al);
                unsigned baddr = baseW + (unsigned)(((c0 + arow) * 72 + nb[q] + acol8) * 2);
                ldsm4t(baddr, bh);
                ldsm4t(baddr + 9216u, bl);
                mma16816(&acc[q][0], ah, &bh[0]);
                mma16816(&acc[q][0], ah, &bl[0]);
                mma16816(&acc[q][0], al, &bh[0]);
                mma16816(&acc[q][4], ah, &bh[2]);
                mma16816(&acc[q][4], ah, &bl[2]);
                mma16816(&acc[q][4], al, &bh[2]);
            }
        }
    }
    __syncthreads();
#pragma unroll
    for (int q = 0; q < 4; q++) {
        if (q >= cnt) break;
#pragma unroll
        for (int h = 0; h < 2; h++) {
            int o0 = nb[q] + h * 8 + ((lane & 3) << 1);
            int r0 = mt[q] * 16 + (lane >> 2);
            zout[o0 * 209 + r0] = acc[q][h * 4 + 0];
            zout[(o0 + 1) * 209 + r0] = acc[q][h * 4 + 1];
            zout[o0 * 209 + r0 + 8] = acc[q][h * 4 + 2];
            zout[(o0 + 1) * 209 + r0 + 8] = acc[q][h * 4 + 3];
        }
    }
    __syncthreads();
    // coalesced store of valid slots
    for (int idx = tid; idx < 64 * 200; idx += 512) {
        int o = idx / 200, sl = idx - o * 200;
        g_y[((size_t)(n * 64 + o) * 512 + t0) * 25 + sl] = zout[o * 209 + sl];
    }
    // BN2 partials (deterministic, valid slots only)
    float* red = (float*)Wh;  // 1024 floats fit in W region
    {
        int o = tid >> 3, sub = tid & 7;
        float a = 0, b = 0;
        for (int sl = sub; sl < 200; sl += 8) {
            float v = zout[o * 209 + sl];
            a += v; b += v * v;
        }
        red[tid] = a; red[512 + tid] = b;
    }
    __syncthreads();
    if (tid < 64) {
        float a = 0, b = 0;
        for (int p = 0; p < 8; p++) { a += red[tid * 8 + p]; b += red[512 + tid * 8 + p]; }
        g_bnS[(size_t)tid * 8192 + n * 64 + tcb] = a;
        g_bnQ[(size_t)tid * 8192 + n * 64 + tcb] = b;
    }
}

// final: out = relu(bn2(g_y) + x), vectorized
__global__ void __launch_bounds__(256) k_bnapply2(
    const float* __restrict__ gm, const float* __restrict__ bt,
    const float* __restrict__ x, float* __restrict__ out)
{
    size_t i4 = (size_t)blockIdx.x * 256 + threadIdx.x;
    size_t flat = i4 * 4;
    int c = (int)((flat / 12800) % 64);
    float m = g_stats[128 + c], r = g_stats[192 + c];
    float sc = r * gm[c];
    float sb = bt[c] - m * sc;
    float4 Y = *(const float4*)&g_y[flat];
    float4 X = *(const float4*)&x[flat];
    float4 O;
    O.x = fmaxf(Y.x * sc + sb + X.x, 0.f);
    O.y = fmaxf(Y.y * sc + sb + X.y, 0.f);
    O.z = fmaxf(Y.z * sc + sb + X.z, 0.f);
    O.w = fmaxf(Y.w * sc + sb + X.w, 0.f);
    *(float4*)&out[flat] = O;
}

// ---------------- launcher ----------------
extern "C" void kernel_launch(void* const* d_in, const int* in_sizes, int n_in,
                              void* d_out, int out_size) {
    const float* x   = (const float*)d_in[0];
    const float* PA  = (const float*)d_in[1];
    const float* alp = (const float*)d_in[2];
    const float* Wa  = (const float*)d_in[3];
    const float* ba  = (const float*)d_in[4];
    const float* Wb  = (const float*)d_in[5];
    const float* bb  = (const float*)d_in[6];
    const float* Wd  = (const float*)d_in[7];
    const float* bng = (const float*)d_in[9];
    const float* bnb = (const float*)d_in[10];
    const float* saw = (const float*)d_in[11];
    const float* sab = (const float*)d_in[12];
    const float* taw = (const float*)d_in[13];
    const float* tab = (const float*)d_in[14];
    const float* f1w = (const float*)d_in[15];
    const float* f1b = (const float*)d_in[16];
    const float* f2w = (const float*)d_in[17];
    const float* f2b = (const float*)d_in[18];
    const float* tw  = (const float*)d_in[19];
    const float* tbg = (const float*)d_in[21];
    const float* tbb = (const float*)d_in[22];
    float* out = (float*)d_out;

    cudaFuncSetAttribute(k_fabgram, cudaFuncAttributeMaxDynamicSharedMemorySize, 106880);
    cudaFuncSetAttribute(k_gcn, cudaFuncAttributeMaxDynamicSharedMemorySize, 75056);
    cudaFuncSetAttribute(k_tcn, cudaFuncAttributeMaxDynamicSharedMemorySize, TCN_SMEM);

    k_prep<<<64, 256>>>(Wd, tw);
    k_fabgram<<<dim3(64, 8), 256, 106880>>>(x, Wa, ba, Wb, bb);
    k_gram2<<<192, 256>>>(PA, alp);
    k_gcn<<<dim3(128, 64), 256, 75056>>>(x);
    k_bnfin<<<64, 256>>>(8192, 0);
    k_bnapply_mt<<<4096, 256>>>(bng, bnb, x);
    k_sattn<<<64, 32>>>(saw, sab);
    k_meanV<<<4096, 256>>>();
    k_tattn<<<64, 256>>>(taw, tab);
    k_cse<<<64, 64>>>(f1w, f1b, f2w, f2b);
    k_tcn<<<dim3(64, 64), 512, TCN_SMEM>>>();
    k_bnfin<<<64, 256>>>(4096, 128);
    k_bnapply2<<<51200, 256>>>(tbg, tbb, x, out);
}